// round 1
// baseline (speedup 1.0000x reference)
#include <cuda_runtime.h>

// Problem constants (from reference)
#define HH    512
#define WW    512
#define PH    8
#define NKH   32
#define NKW   32
#define NK    1024          // NKH*NKW
#define NC    33            // (528/16) stride cells per dim
#define BATCH 64
#define BT    8             // batches per block (one warp per batch)

// Per-(b, n, quadrant) partial sums. Every slot has exactly one producing
// (cell, batch) pair -> written exactly once per launch, no init needed.
__device__ float g_scratch[BATCH * NK * 4];

// Pass 1: one block per (stride cell, batch tile).
// Cell (Ri,Ci) covers padded pixels [16Ri,16Ri+16) x [16Ci,16Ci+16).
// Those pixels belong to windows (Ri-i, Ci-j), i,j in {0,1}, hitting kernel
// offsets (dy+16i, dx+16j). Block caches the 4 relevant 16x16 weight
// quadrants in smem (4KB); each warp handles one batch image.
__global__ __launch_bounds__(256) void bslc_pass1(
    const float* __restrict__ x,       // (B,1,512,512)
    const float* __restrict__ weight)  // (NK, 1024)
{
    const int cell = blockIdx.x;          // 0..1088
    const int Ri   = cell / NC;
    const int Ci   = cell % NC;
    const int tid  = threadIdx.x;
    const int lane = tid & 31;
    const int warp = tid >> 5;

    __shared__ float4 wsh[256];           // [pixel-in-cell] -> (q0,q1,q2,q3)

    // Window index + validity per quadrant q=(i,j)
    int  nq[4];
    bool vq[4];
#pragma unroll
    for (int q = 0; q < 4; q++) {
        const int i = q >> 1, j = q & 1;
        const int r = Ri - i, c = Ci - j;
        const bool v = (r >= 0) && (r < NKH) && (c >= 0) && (c < NKW);
        vq[q] = v;
        nq[q] = v ? (r * NKW + c) : 0;
    }

    // Cooperative weight quadrant load: element tid = (dy,dx) of the cell.
    {
        const int dy = tid >> 4, dx = tid & 15;
        float w[4];
#pragma unroll
        for (int q = 0; q < 4; q++) {
            const int i = q >> 1, j = q & 1;
            w[q] = vq[q]
                 ? weight[nq[q] * 1024 + (dy + 16 * i) * 32 + (dx + 16 * j)]
                 : 0.0f;
        }
        wsh[tid] = make_float4(w[0], w[1], w[2], w[3]);
    }
    __syncthreads();

    // One warp per batch image.
    const int b = blockIdx.y * BT + warp;
    const float* __restrict__ xb = x + (size_t)b * HH * WW;

    float a0 = 0.f, a1 = 0.f, a2 = 0.f, a3 = 0.f;
#pragma unroll
    for (int s = 0; s < 8; s++) {
        const int p  = s * 32 + lane;     // pixel index within cell
        const int dy = p >> 4, dx = p & 15;
        const int uy = Ri * 16 + dy - PH; // unpadded coords
        const int ux = Ci * 16 + dx - PH;
        float xv = 0.0f;
        if ((unsigned)uy < (unsigned)HH && (unsigned)ux < (unsigned)WW)
            xv = xb[uy * WW + ux];
        const float4 w4 = wsh[p];
        a0 = fmaf(xv, w4.x, a0);
        a1 = fmaf(xv, w4.y, a1);
        a2 = fmaf(xv, w4.z, a2);
        a3 = fmaf(xv, w4.w, a3);
    }

    // Warp reduction over the 256 cell pixels.
#pragma unroll
    for (int off = 16; off; off >>= 1) {
        a0 += __shfl_xor_sync(0xffffffffu, a0, off);
        a1 += __shfl_xor_sync(0xffffffffu, a1, off);
        a2 += __shfl_xor_sync(0xffffffffu, a2, off);
        a3 += __shfl_xor_sync(0xffffffffu, a3, off);
    }

    if (lane == 0) {
        const float acc[4] = {a0, a1, a2, a3};
#pragma unroll
        for (int q = 0; q < 4; q++)
            if (vq[q])
                g_scratch[((size_t)b * NK + nq[q]) * 4 + q] = acc[q];
    }
}

// Pass 2: out[b,n] = sum of 4 quadrant partials + bias[n]
__global__ __launch_bounds__(256) void bslc_pass2(
    const float* __restrict__ bias,
    float* __restrict__ out)
{
    const int idx = blockIdx.x * blockDim.x + threadIdx.x;   // b*NK + n
    const float4 v = reinterpret_cast<const float4*>(g_scratch)[idx];
    out[idx] = v.x + v.y + v.z + v.w + bias[idx & (NK - 1)];
}

extern "C" void kernel_launch(void* const* d_in, const int* in_sizes, int n_in,
                              void* d_out, int out_size)
{
    const float* x      = (const float*)d_in[0];   // (64,1,512,512) fp32
    const float* weight = (const float*)d_in[1];   // (1024,1024)    fp32
    const float* bias   = (const float*)d_in[2];   // (1024,)        fp32
    float*       out    = (float*)d_out;           // (64,32,32)     fp32

    dim3 grid1(NC * NC, BATCH / BT);               // 1089 x 8 blocks
    bslc_pass1<<<grid1, 256>>>(x, weight);

    bslc_pass2<<<(BATCH * NK) / 256, 256>>>(bias, out);
}

// round 2
// speedup vs baseline: 1.2624x; 1.2624x over previous
#include <cuda_runtime.h>

#define HH    512
#define WW    512
#define PAD   8
#define NKH   32
#define NKW   32
#define NK    1024
#define NC    33            // stride cells per dim (528/16)
#define BATCH 64
#define BPG   32            // batches per grid.y slice
#define BPW   4             // batches per warp (8 warps * 4 = 32)

// Per-(b, n, quadrant) partials. Each slot has exactly one producer.
__device__ float g_scratch[BATCH * NK * 4];

// One block per (stride cell, batch half). Cell (Ri,Ci) covers padded pixels
// [16Ri,16Ri+16) x [16Ci,16Ci+16); these feed windows (Ri-i, Ci-j), i,j in
// {0,1}, at kernel offsets (dy+16i, dx+16j). Weights for the 4 quadrants are
// cached in REGISTERS (8 float4/lane); x is read once as predicated float4.
__global__ __launch_bounds__(256) void bslc_pass1(
    const float* __restrict__ x,       // (B,1,512,512)
    const float* __restrict__ weight)  // (NK,1024)
{
    const int cell = blockIdx.x;
    const int Ri = cell / NC, Ci = cell % NC;
    const int tid  = threadIdx.x;
    const int lane = tid & 31;
    const int warp = tid >> 5;

    // Window index + validity per quadrant q = (i,j)
    int nq[4]; bool vq[4];
#pragma unroll
    for (int q = 0; q < 4; q++) {
        const int i = q >> 1, j = q & 1;
        const int r = Ri - i, c = Ci - j;
        vq[q] = (r >= 0) && (r < NKH) && (c >= 0) && (c < NKW);
        nq[q] = vq[q] ? (r * NKW + c) : 0;
    }
    // Pre-resolve the dynamic lane->quadrant select (avoid local-mem indexing)
    const int  nsel = (lane == 0) ? nq[0] : (lane == 1) ? nq[1]
                    : (lane == 2) ? nq[2] : nq[3];
    const bool vsel = (lane == 0) ? vq[0] : (lane == 1) ? vq[1]
                    : (lane == 2) ? vq[2] : vq[3];

    // Lane covers pixel-quads qd = lane and lane+32 of the 16x16 cell.
    float4 wreg[2][4];
    bool   xok[2];
    long   xoff[2];
#pragma unroll
    for (int s = 0; s < 2; s++) {
        const int qd  = lane + 32 * s;
        const int dy  = qd >> 2;
        const int dx4 = (qd & 3) << 2;
#pragma unroll
        for (int q = 0; q < 4; q++) {
            const int i = q >> 1, j = q & 1;
            float4 w = make_float4(0.f, 0.f, 0.f, 0.f);
            if (vq[q])
                w = *reinterpret_cast<const float4*>(
                        weight + nq[q] * 1024 + (dy + 16 * i) * 32 + (dx4 + 16 * j));
            wreg[s][q] = w;
        }
        const int uy = Ri * 16 + dy  - PAD;   // unpadded row
        const int ux = Ci * 16 + dx4 - PAD;   // unpadded col (float4-aligned)
        xok[s]  = ((unsigned)uy < (unsigned)HH) && ((unsigned)ux <= (unsigned)(WW - 4));
        xoff[s] = (long)uy * WW + ux;
    }

    const int b0 = blockIdx.y * BPG + warp * BPW;
    const float* __restrict__ xb = x + (size_t)b0 * (HH * WW);

#define LDX(t, s) ( xok[s] ? *reinterpret_cast<const float4*>(xb + (size_t)(t) * (HH * WW) + xoff[s]) \
                           : make_float4(0.f, 0.f, 0.f, 0.f) )

    // Software pipeline over the 4 batches (depth 2)
    float4 c0 = LDX(0, 0), c1 = LDX(0, 1);
    float4 n0 = LDX(1, 0), n1 = LDX(1, 1);

#pragma unroll
    for (int t = 0; t < BPW; t++) {
        float4 p0, p1;
        if (t + 2 < BPW) { p0 = LDX(t + 2, 0); p1 = LDX(t + 2, 1); }

        float a0 = 0.f, a1 = 0.f, a2 = 0.f, a3 = 0.f;
        // 32 FMAs: 2 quads x 4 quadrants x float4
        a0 = fmaf(c0.x, wreg[0][0].x, a0); a0 = fmaf(c0.y, wreg[0][0].y, a0);
        a0 = fmaf(c0.z, wreg[0][0].z, a0); a0 = fmaf(c0.w, wreg[0][0].w, a0);
        a1 = fmaf(c0.x, wreg[0][1].x, a1); a1 = fmaf(c0.y, wreg[0][1].y, a1);
        a1 = fmaf(c0.z, wreg[0][1].z, a1); a1 = fmaf(c0.w, wreg[0][1].w, a1);
        a2 = fmaf(c0.x, wreg[0][2].x, a2); a2 = fmaf(c0.y, wreg[0][2].y, a2);
        a2 = fmaf(c0.z, wreg[0][2].z, a2); a2 = fmaf(c0.w, wreg[0][2].w, a2);
        a3 = fmaf(c0.x, wreg[0][3].x, a3); a3 = fmaf(c0.y, wreg[0][3].y, a3);
        a3 = fmaf(c0.z, wreg[0][3].z, a3); a3 = fmaf(c0.w, wreg[0][3].w, a3);
        a0 = fmaf(c1.x, wreg[1][0].x, a0); a0 = fmaf(c1.y, wreg[1][0].y, a0);
        a0 = fmaf(c1.z, wreg[1][0].z, a0); a0 = fmaf(c1.w, wreg[1][0].w, a0);
        a1 = fmaf(c1.x, wreg[1][1].x, a1); a1 = fmaf(c1.y, wreg[1][1].y, a1);
        a1 = fmaf(c1.z, wreg[1][1].z, a1); a1 = fmaf(c1.w, wreg[1][1].w, a1);
        a2 = fmaf(c1.x, wreg[1][2].x, a2); a2 = fmaf(c1.y, wreg[1][2].y, a2);
        a2 = fmaf(c1.z, wreg[1][2].z, a2); a2 = fmaf(c1.w, wreg[1][2].w, a2);
        a3 = fmaf(c1.x, wreg[1][3].x, a3); a3 = fmaf(c1.y, wreg[1][3].y, a3);
        a3 = fmaf(c1.z, wreg[1][3].z, a3); a3 = fmaf(c1.w, wreg[1][3].w, a3);

#pragma unroll
        for (int off = 16; off; off >>= 1) {
            a0 += __shfl_xor_sync(0xffffffffu, a0, off);
            a1 += __shfl_xor_sync(0xffffffffu, a1, off);
            a2 += __shfl_xor_sync(0xffffffffu, a2, off);
            a3 += __shfl_xor_sync(0xffffffffu, a3, off);
        }

        if (lane < 4 && vsel) {
            const float v = (lane == 0) ? a0 : (lane == 1) ? a1
                          : (lane == 2) ? a2 : a3;
            g_scratch[((size_t)(b0 + t) * NK + nsel) * 4 + lane] = v;
        }

        c0 = n0; c1 = n1; n0 = p0; n1 = p1;
    }
#undef LDX
}

// Pass 2: out[b,n] = sum of 4 quadrant partials + bias[n]
__global__ __launch_bounds__(256) void bslc_pass2(
    const float* __restrict__ bias,
    float* __restrict__ out)
{
    const int idx = blockIdx.x * blockDim.x + threadIdx.x;   // b*NK + n
    const float4 v = reinterpret_cast<const float4*>(g_scratch)[idx];
    out[idx] = v.x + v.y + v.z + v.w + bias[idx & (NK - 1)];
}

extern "C" void kernel_launch(void* const* d_in, const int* in_sizes, int n_in,
                              void* d_out, int out_size)
{
    const float* x      = (const float*)d_in[0];   // (64,1,512,512) fp32
    const float* weight = (const float*)d_in[1];   // (1024,1024)    fp32
    const float* bias   = (const float*)d_in[2];   // (1024,)        fp32
    float*       out    = (float*)d_out;           // (64,32,32)     fp32

    dim3 grid1(NC * NC, BATCH / BPG);              // 1089 x 2 fat blocks
    bslc_pass1<<<grid1, 256>>>(x, weight);

    bslc_pass2<<<(BATCH * NK) / 256, 256>>>(bias, out);
}